// round 3
// baseline (speedup 1.0000x reference)
#include <cuda_runtime.h>
#include <math_constants.h>

#define BB 4096
#define PP 128
#define GG 128

#define SCX (8000.0f / 79.0f)
#define SCY (8000.0f / 79.0f)
#define SCZ (2000.0f / 19.0f)
#define BX (-4000.0f)
#define BY (-4000.0f)
#define BZ (0.0f)

#define DIST_THRESH_SQ (500.0f * 500.0f)
#define BBOX_THRESH 0.1f

// ---- packed f32x2 helpers (sm_103a) ----
__device__ __forceinline__ unsigned long long pack2(float lo, float hi) {
    unsigned long long r;
    asm("mov.b64 %0, {%1, %2};" : "=l"(r) : "f"(lo), "f"(hi));
    return r;
}
__device__ __forceinline__ void unpack2(unsigned long long v, float& lo, float& hi) {
    asm("mov.b64 {%0, %1}, %2;" : "=f"(lo), "=f"(hi) : "l"(v));
}
__device__ __forceinline__ unsigned long long fma2(unsigned long long a, unsigned long long b,
                                                   unsigned long long c) {
    unsigned long long r;
    asm("fma.rn.f32x2 %0, %1, %2, %3;" : "=l"(r) : "l"(a), "l"(b), "l"(c));
    return r;
}

// Per-proposal state: argmin over g of e(g) = h_g - c.r_g (same ordering as d^2)
struct Prop {
    unsigned long long cxx, cyy, czz;  // broadcast packed coords
    float cx, cy, cz, cc;              // scalars + |c|^2
    float b0, b1, b2, b3;              // 4 min chains (residue mod 4)
    int   q0, q1, q2, q3;              // block index per chain
};

__global__ __launch_bounds__(64)
void proposal_layer_kernel(const int*   __restrict__ topk_index,      // [B,P,3]
                           const float* __restrict__ topk_confs,      // [B,P]
                           const float* __restrict__ match_bbox_preds,// [B,P,2]
                           const float* __restrict__ roots_3d,        // [B,G,3]
                           const float* __restrict__ gt_bbox,         // [B,G,2]
                           const int*   __restrict__ num_person,      // [B]
                           float*       __restrict__ out)             // [B,P,7]
{
    const int b = blockIdx.x;
    const int t = threadIdx.x;  // 0..63, each thread owns proposals t and t+64

    __shared__ __align__(16) float s_nx[GG];   // -rx
    __shared__ __align__(16) float s_ny[GG];   // -ry
    __shared__ __align__(16) float s_nz[GG];   // -rz
    __shared__ __align__(16) float s_h[GG];    // |r|^2 / 2
    __shared__ float2 s_bbox[GG];
    __shared__ float  s_out[PP * 7];

    // stage 2 g-entries per thread
    #pragma unroll
    for (int k = 0; k < 2; ++k) {
        const int g = t + k * 64;
        const float* r = roots_3d + ((size_t)b * GG + g) * 3;
        float rx = r[0], ry = r[1], rz = r[2];
        s_nx[g] = -rx;
        s_ny[g] = -ry;
        s_nz[g] = -rz;
        s_h[g]  = 0.5f * __fmaf_rn(rz, rz, __fmaf_rn(ry, ry, rx * rx));
        const float* gb = gt_bbox + ((size_t)b * GG + g) * 2;
        s_bbox[g] = make_float2(gb[0], gb[1]);
    }
    const int n = num_person[b];
    __syncthreads();

    // per-proposal setup (2 proposals per thread)
    Prop pr[2];
    float conf[2], pb0[2], pb1[2];
    #pragma unroll
    for (int k = 0; k < 2; ++k) {
        const int p = t + k * 64;
        const int* ti = topk_index + ((size_t)b * PP + p) * 3;
        float cx = (float)ti[0] * SCX + BX;
        float cy = (float)ti[1] * SCY + BY;
        float cz = (float)ti[2] * SCZ + BZ;
        pr[k].cx = cx; pr[k].cy = cy; pr[k].cz = cz;
        pr[k].cc = __fmaf_rn(cz, cz, __fmaf_rn(cy, cy, cx * cx));
        pr[k].cxx = pack2(cx, cx);
        pr[k].cyy = pack2(cy, cy);
        pr[k].czz = pack2(cz, cz);
        pr[k].b0 = pr[k].b1 = pr[k].b2 = pr[k].b3 = CUDART_INF_F;
        pr[k].q0 = pr[k].q1 = pr[k].q2 = pr[k].q3 = 0;
        conf[k] = topk_confs[(size_t)b * PP + p];
        const float* mp = match_bbox_preds + ((size_t)b * PP + p) * 2;
        pb0[k] = mp[0];
        pb1[k] = mp[1];
    }

    const ulonglong2* px = (const ulonglong2*)s_nx;
    const ulonglong2* py = (const ulonglong2*)s_ny;
    const ulonglong2* pz = (const ulonglong2*)s_nz;
    const ulonglong2* ph = (const ulonglong2*)s_h;

    const int nb = n >> 2;
    #pragma unroll 2
    for (int q = 0; q < nb; ++q) {
        ulonglong2 X = px[q];  // 4 LDS.128 feed 8 (p,g) pairs
        ulonglong2 Y = py[q];
        ulonglong2 Z = pz[q];
        ulonglong2 H = ph[q];

        #pragma unroll
        for (int k = 0; k < 2; ++k) {
            unsigned long long eA =
                fma2(pr[k].cxx, X.x, fma2(pr[k].cyy, Y.x, fma2(pr[k].czz, Z.x, H.x)));
            unsigned long long eB =
                fma2(pr[k].cxx, X.y, fma2(pr[k].cyy, Y.y, fma2(pr[k].czz, Z.y, H.y)));
            float s0, s1, s2, s3;
            unpack2(eA, s0, s1);
            unpack2(eB, s2, s3);
            if (s0 < pr[k].b0) { pr[k].b0 = s0; pr[k].q0 = q; }
            if (s1 < pr[k].b1) { pr[k].b1 = s1; pr[k].q1 = q; }
            if (s2 < pr[k].b2) { pr[k].b2 = s2; pr[k].q2 = q; }
            if (s3 < pr[k].b3) { pr[k].b3 = s3; pr[k].q3 = q; }
        }
    }

    #pragma unroll
    for (int k = 0; k < 2; ++k) {
        // merge chains (strict <)
        float bd = pr[k].b0; int bi = (pr[k].q0 << 2);
        if (pr[k].b1 < bd) { bd = pr[k].b1; bi = (pr[k].q1 << 2) + 1; }
        if (pr[k].b2 < bd) { bd = pr[k].b2; bi = (pr[k].q2 << 2) + 2; }
        if (pr[k].b3 < bd) { bd = pr[k].b3; bi = (pr[k].q3 << 2) + 3; }

        // scalar tail (same fma nesting as packed lanes)
        for (int g = (nb << 2); g < n; ++g) {
            float e = __fmaf_rn(pr[k].cx, s_nx[g],
                     __fmaf_rn(pr[k].cy, s_ny[g],
                     __fmaf_rn(pr[k].cz, s_nz[g], s_h[g])));
            if (e < bd) { bd = e; bi = g; }
        }

        // d2 = 2*e + cc ; matched <=> d2 <= 500^2  <=> e <= (500^2 - cc)/2
        const float thresh_e = __fmaf_rn(-0.5f, pr[k].cc, 0.5f * DIST_THRESH_SQ);
        const bool matched = !(bd > thresh_e);
        const float p2g = matched ? (float)bi : -1.0f;

        float2 mb = s_bbox[bi];
        bool ow = matched && ((pb0[k] < mb.x - BBOX_THRESH) || (pb1[k] < mb.y - BBOX_THRESH));
        const float o5 = ow ? mb.x : pb0[k];
        const float o6 = ow ? mb.y : pb1[k];

        const int p = t + k * 64;
        float* so = s_out + p * 7;   // stride 7 -> conflict-free
        so[0] = pr[k].cx; so[1] = pr[k].cy; so[2] = pr[k].cz;
        so[3] = p2g; so[4] = conf[k];
        so[5] = o5;  so[6] = o6;
    }
    __syncthreads();

    // coalesced store of 896 floats by 64 threads
    float* ob = out + (size_t)b * (PP * 7);
    #pragma unroll
    for (int i = t; i < PP * 7; i += 64)
        ob[i] = s_out[i];
}

extern "C" void kernel_launch(void* const* d_in, const int* in_sizes, int n_in,
                              void* d_out, int out_size)
{
    const int*   topk_index       = (const int*)  d_in[0];
    const float* topk_confs       = (const float*)d_in[1];
    const float* match_bbox_preds = (const float*)d_in[2];
    const float* roots_3d         = (const float*)d_in[3];
    const float* gt_bbox          = (const float*)d_in[4];
    const int*   num_person       = (const int*)  d_in[5];
    float* out = (float*)d_out;

    proposal_layer_kernel<<<BB, 64>>>(topk_index, topk_confs, match_bbox_preds,
                                      roots_3d, gt_bbox, num_person, out);
}